// round 15
// baseline (speedup 1.0000x reference)
#include <cuda_runtime.h>
#include <cstdint>
#include <math.h>

#define B_    64
#define N_    20000
#define F1_   512
#define F2_   256
#define D_    128
#define KSEL_ 20
#define ROWS_ (B_ * KSEL_)

typedef unsigned long long u64t;

// ---------------- static device scratch (no allocations allowed) ----------------
__device__ float    g_kpbT[D_ * N_];     // TRANSPOSED: [d][n]
__device__ float    g_Q[B_ * D_];        // Q = pe@Wq + bq
__device__ float    g_qp2f[D_ * B_];     // q_part, packed layout [d][b]
__device__ float    g_m[B_ * N_];        // logits = sim / TEMP
__device__ unsigned g_mmax_bits[B_];     // per-b max of logits, encoded
__device__ int      g_sel[ROWS_];        // argmax indices
__device__ __align__(16) float g_Wf4[64 * D_ * 4];  // fused weight, packed [f4][d][4]
__device__ float    g_bias[D_];          // bk@W1[D:] + b1
__device__ __align__(16) unsigned short g_m16[(size_t)ROWS_ * N_];  // mant>>7 table

// ---------------- f32x2 packed helpers ----------------
__device__ __forceinline__ u64t pack2(float lo, float hi) {
    u64t r; asm("mov.b64 %0,{%1,%2};" : "=l"(r) : "f"(lo), "f"(hi)); return r;
}
__device__ __forceinline__ float2 unpack2(u64t v) {
    float2 r; asm("mov.b64 {%0,%1},%2;" : "=f"(r.x), "=f"(r.y) : "l"(v)); return r;
}
__device__ __forceinline__ u64t add2(u64t a, u64t b) {
    u64t r; asm("add.rn.f32x2 %0,%1,%2;" : "=l"(r) : "l"(a), "l"(b)); return r;
}
__device__ __forceinline__ u64t fma2(u64t a, u64t b, u64t c) {
    u64t r; asm("fma.rn.f32x2 %0,%1,%2,%3;" : "=l"(r) : "l"(a), "l"(b), "l"(c)); return r;
}
__device__ __forceinline__ u64t abs2(u64t a) { return a & 0x7FFFFFFF7FFFFFFFULL; }

__device__ __forceinline__ unsigned enc_f(float z) {
    unsigned u = __float_as_uint(z);
    return (u & 0x80000000u) ? ~u : (u | 0x80000000u);
}
__device__ __forceinline__ float dec_f(unsigned e) {
    unsigned u = (e & 0x80000000u) ? (e & 0x7fffffffu) : ~e;
    return __uint_as_float(u);
}

// ---------------- threefry2x32 partitionable (verified bit-exact) ----------------
__device__ __forceinline__ unsigned madu(unsigned a, unsigned one, unsigned c) {
    unsigned r; asm("mad.lo.s32 %0,%1,%2,%3;" : "=r"(r) : "r"(a), "r"(one), "r"(c)); return r;
}
template<int IMADD>
__device__ __forceinline__ unsigned addsel(unsigned a, unsigned b, unsigned one) {
    return IMADD ? madu(b, one, a) : (a + b);
}
#define TFR2(r) { x0 = addsel<IMADD>(x0, x1, one); x1 = __funnelshift_l(x1, x1, (r)); x1 ^= x0; }

template<int IMADD>
__device__ __forceinline__ unsigned tf_bits(unsigned idx, unsigned one) {
    const unsigned ks1 = 42u, ks2 = 0x1BD11BF0u;   // ks0 = 0
    unsigned x1r = idx + ks1;
    unsigned x0 = x1r;
    unsigned x1 = __funnelshift_l(x1r, x1r, 13) ^ x0;
    TFR2(15) TFR2(26) TFR2(6);
    x0 = addsel<IMADD>(x0, ks1, one);  x1 = addsel<IMADD>(x1, ks2 + 1u, one);
    TFR2(17) TFR2(29) TFR2(16) TFR2(24);
    x0 = addsel<IMADD>(x0, ks2, one);  x1 = addsel<IMADD>(x1, 2u, one);
    TFR2(13) TFR2(15) TFR2(26) TFR2(6);
    x1 = addsel<IMADD>(x1, ks1 + 3u, one);   // x0 += 0
    TFR2(17) TFR2(29) TFR2(16) TFR2(24);
    x0 = addsel<IMADD>(x0, ks1, one);  x1 = addsel<IMADD>(x1, ks2 + 4u, one);
    TFR2(13) TFR2(15) TFR2(26) TFR2(6);
    x0 = addsel<IMADD>(x0, ks2, one);  x1 = addsel<IMADD>(x1, 5u, one);
    return x0 ^ x1;
}

// ---------------- K0 (stream 2): hash table -- runs concurrent with prep/gene/logits ----
__global__ __launch_bounds__(256) void k_hash(unsigned one) {
    const int bid = blockIdx.x;
    const int row = bid >> 3;
    const int n0 = (bid & 7) * 2500;
    const unsigned base = (unsigned)row * (unsigned)N_;
    unsigned short* dst = g_m16 + (size_t)row * N_;
    #pragma unroll
    for (int i = 0; i < 10; i++) {
        int off = i * 256 + threadIdx.x;
        if (off < 2500) {
            int n = n0 + off;
            unsigned bits = tf_bits<1>(base + (unsigned)n, one);  // adds on IMAD/fma pipe
            dst[n] = (unsigned short)(bits >> 16);                // == mant >> 7
        }
    }
}

// ---------------- K1: fused prep -- Q/q_part (0..63), Wf (64..319), bias (320) ----
__global__ __launch_bounds__(128) void k_prep(const float* __restrict__ pe,
                                              const float* __restrict__ Wq,
                                              const float* __restrict__ bq,
                                              const float* __restrict__ Wk,
                                              const float* __restrict__ bk,
                                              const float* __restrict__ W1,
                                              const float* __restrict__ b1) {
    const int d = threadIdx.x;
    if (blockIdx.x < 64) {
        __shared__ float pes[F1_];
        __shared__ float Qs[D_];
        const int b = blockIdx.x;
        if (d == 0) g_mmax_bits[b] = 0u;       // reset per replay
        for (int i = d; i < F1_; i += 128) pes[i] = pe[b * F1_ + i];
        __syncthreads();
        float acc = bq[d];
        #pragma unroll 4
        for (int f = 0; f < F1_; f++) acc = fmaf(pes[f], Wq[f * D_ + d], acc);
        g_Q[b * D_ + d] = acc;
        Qs[d] = acc;
        __syncthreads();
        float a2 = 0.f;
        #pragma unroll 4
        for (int j = 0; j < D_; j++) a2 = fmaf(Qs[j], W1[j * D_ + d], a2);
        g_qp2f[d * B_ + b] = a2;
    } else {
        __shared__ float rowv[D_];
        const float* W1p = W1 + D_ * D_;
        if (blockIdx.x < 320) {
            const int f = blockIdx.x - 64;
            rowv[d] = Wk[f * D_ + d];
            __syncthreads();
            float acc = 0.f;
            #pragma unroll 4
            for (int j = 0; j < D_; j++) acc = fmaf(rowv[j], W1p[j * D_ + d], acc);
            g_Wf4[(((f >> 2) * D_) + d) * 4 + (f & 3)] = acc;
        } else {
            rowv[d] = bk[d];
            __syncthreads();
            float acc = b1[d];
            #pragma unroll 4
            for (int j = 0; j < D_; j++) acc = fmaf(rowv[j], W1p[j * D_ + d], acc);
            g_bias[d] = acc;
        }
    }
}

// ---------------- K2: kpbT = (ge @ Wf + bias)^T ----------------
__global__ __launch_bounds__(128) void k_gene(const float* __restrict__ ge) {
    __shared__ __align__(16) float ges[32][256];
    const int d = threadIdx.x;
    const int n0 = blockIdx.x * 32;

    const float4* ge4 = (const float4*)(ge + n0 * F2_);
    for (int i = d; i < 32 * 64; i += 128) {
        int r = i >> 6, c = i & 63;
        *(float4*)&ges[r][c * 4] = ge4[r * 64 + c];
    }
    __syncthreads();

    float acc[32];
    const float bd = g_bias[d];
    #pragma unroll
    for (int r = 0; r < 32; r++) acc[r] = bd;

    const float4* Wf4 = (const float4*)g_Wf4;
    float4 wnext = Wf4[d];
    for (int f4 = 0; f4 < 64; f4++) {
        const float4 w = wnext;
        if (f4 < 63) wnext = Wf4[(f4 + 1) * D_ + d];
        const int f = f4 * 4;
        #pragma unroll
        for (int r = 0; r < 32; r++) {
            float4 x = *(const float4*)&ges[r][f];
            acc[r] = fmaf(x.x, w.x, acc[r]); acc[r] = fmaf(x.y, w.y, acc[r]);
            acc[r] = fmaf(x.z, w.z, acc[r]); acc[r] = fmaf(x.w, w.w, acc[r]);
        }
    }

    __syncthreads();
    float* st = (float*)ges;
    #pragma unroll
    for (int r = 0; r < 32; r++) st[d * 33 + r] = acc[r];
    __syncthreads();
    float* dst = g_kpbT + d * N_ + n0;
    #pragma unroll
    for (int j = 0; j < 8; j++) {
        float4 v;
        v.x = st[d * 33 + 4*j + 0]; v.y = st[d * 33 + 4*j + 1];
        v.z = st[d * 33 + 4*j + 2]; v.w = st[d * 33 + 4*j + 3];
        *(float4*)(dst + 4*j) = v;
    }
}

// ---------------- K3: logits m[b,n] -- 4 b x 4 n per thread, pipelined d-loop ----------------
__global__ __launch_bounds__(128) void k_logits(const float* __restrict__ w2,
                                                const float* __restrict__ b2p) {
    __shared__ u64t s_q2[D_][4];
    __shared__ u64t s_wa[D_], s_wb[D_];
    const int tid = threadIdx.x;
    const int lane = tid & 31;
    const int b0 = blockIdx.y * 4;

    for (int i = tid; i < 512; i += 128) {
        int d = i >> 2, j = i & 3;
        float q = g_qp2f[d * B_ + b0 + j];
        s_q2[d][j] = pack2(q, q);
    }
    {
        float w = w2[tid];
        s_wa[tid] = pack2(0.55f * w, 0.55f * w);
        s_wb[tid] = pack2(0.45f * w, 0.45f * w);
    }
    __syncthreads();

    const int n = (blockIdx.x * 128 + tid) * 4;
    const int nc = n <= N_ - 4 ? n : N_ - 4;
    const float* kT = g_kpbT + nc;

    u64t accA[4][2], accB[4][2];
    #pragma unroll
    for (int b = 0; b < 4; b++) { accA[b][0]=accA[b][1]=0ull; accB[b][0]=accB[b][1]=0ull; }

    float4 kc[4];
    #pragma unroll
    for (int i = 0; i < 4; i++) kc[i] = *(const float4*)(kT + i * N_);

    #pragma unroll 2
    for (int d0 = 0; d0 < D_ - 4; d0 += 4) {
        float4 cur[4];
        #pragma unroll
        for (int i = 0; i < 4; i++) cur[i] = kc[i];
        #pragma unroll
        for (int i = 0; i < 4; i++) kc[i] = *(const float4*)(kT + (d0 + 4 + i) * N_);
        #pragma unroll
        for (int i = 0; i < 4; i++) {
            const int d = d0 + i;
            u64t kn01 = pack2(cur[i].x, cur[i].y);
            u64t kn23 = pack2(cur[i].z, cur[i].w);
            u64t wa = s_wa[d], wb = s_wb[d];
            #pragma unroll
            for (int b = 0; b < 4; b++) {
                u64t q = s_q2[d][b];
                u64t x0 = add2(q, kn01);
                u64t x1 = add2(q, kn23);
                accA[b][0] = fma2(x0, wa, accA[b][0]);
                accB[b][0] = fma2(abs2(x0), wb, accB[b][0]);
                accA[b][1] = fma2(x1, wa, accA[b][1]);
                accB[b][1] = fma2(abs2(x1), wb, accB[b][1]);
            }
        }
    }
    #pragma unroll
    for (int i = 0; i < 4; i++) {
        const int d = D_ - 4 + i;
        u64t kn01 = pack2(kc[i].x, kc[i].y);
        u64t kn23 = pack2(kc[i].z, kc[i].w);
        u64t wa = s_wa[d], wb = s_wb[d];
        #pragma unroll
        for (int b = 0; b < 4; b++) {
            u64t q = s_q2[d][b];
            u64t x0 = add2(q, kn01);
            u64t x1 = add2(q, kn23);
            accA[b][0] = fma2(x0, wa, accA[b][0]);
            accB[b][0] = fma2(abs2(x0), wb, accB[b][0]);
            accA[b][1] = fma2(x1, wa, accA[b][1]);
            accB[b][1] = fma2(abs2(x1), wb, accB[b][1]);
        }
    }

    const float b2 = *b2p;
    float vals[4][4];
    #pragma unroll
    for (int b = 0; b < 4; b++) {
        float2 a01 = unpack2(add2(accA[b][0], accB[b][0]));
        float2 a23 = unpack2(add2(accA[b][1], accB[b][1]));
        vals[b][0] = (a01.x + b2) * 2.0f;   // /TEMP, TEMP=0.5
        vals[b][1] = (a01.y + b2) * 2.0f;
        vals[b][2] = (a23.x + b2) * 2.0f;
        vals[b][3] = (a23.y + b2) * 2.0f;
    }
    if (n <= N_ - 4) {
        #pragma unroll
        for (int b = 0; b < 4; b++) {
            float4 v; v.x = vals[b][0]; v.y = vals[b][1]; v.z = vals[b][2]; v.w = vals[b][3];
            *(float4*)(g_m + (b0 + b) * N_ + n) = v;
        }
    }
    #pragma unroll
    for (int b = 0; b < 4; b++) {
        float m = fmaxf(fmaxf(vals[b][0], vals[b][1]), fmaxf(vals[b][2], vals[b][3]));
        m = fmaxf(m, __shfl_xor_sync(0xffffffffu, m, 16));
        m = fmaxf(m, __shfl_xor_sync(0xffffffffu, m, 8));
        m = fmaxf(m, __shfl_xor_sync(0xffffffffu, m, 4));
        m = fmaxf(m, __shfl_xor_sync(0xffffffffu, m, 2));
        m = fmaxf(m, __shfl_xor_sync(0xffffffffu, m, 1));
        if (lane == 0) atomicMax(&g_mmax_bits[b0 + b], enc_f(m));
    }
}

// ---------------- K4: argmax over 16-bit table, SIMD prune + exact survivors ----------
__device__ __forceinline__ void amx_surv(const float* __restrict__ mrow,
                                         float mmax, unsigned base,
                                         int n, int* s_uthm,
                                         float& lbest, int& libest) {
    unsigned bits = tf_bits<0>(base + (unsigned)n, 1u);
    unsigned mant = bits >> 9;
    float u = fmaxf(__uint_as_float(mant | 0x3f800000u) - 1.0f, 1.17549435e-38f);
    float g = -logf(-logf(u));          // bit-matches XLA path
    float z = mrow[n] + g;
    if (z > lbest || (z == lbest && n < libest)) {
        lbest = z; libest = n;
        float nuth = expf(-expf(-(z - mmax))) - 2e-6f;
        if (nuth > 0.f) atomicMax(s_uthm, (int)(nuth * 8388608.0f));
    }
}

__global__ __launch_bounds__(256) void k_amx_lite() {
    const int row = blockIdx.x;            // b*KSEL + k
    const int b = row / KSEL_;
    const float* mrow = g_m + b * N_;
    const float mmax = dec_f(g_mmax_bits[b]);
    const unsigned base = (unsigned)row * (unsigned)N_;
    __shared__ int s_uthm;
    __shared__ float szred[256];
    __shared__ int   sired[256];
    const int tid = threadIdx.x;
    if (tid == 0) s_uthm = -1;
    __syncthreads();

    float lbest = -1e30f;
    int   libest = 0x7fffffff;

    // seed threshold from candidates 0..255 (exact path) -> main loop prunes hard
    amx_surv(mrow, mmax, base, tid, &s_uthm, lbest, libest);
    __syncthreads();

    const uint4* t16 = (const uint4*)(g_m16 + (size_t)row * N_);  // 8 cands / load
    for (int i = 0; i < 10; i++) {         // 2500 uint4 per row
        const int u = i * 256 + tid;
        if (u < 2500) {
            int uth = *(volatile int*)&s_uthm;
            int th16 = uth < 0 ? 0 : (uth >> 7);
            if (th16 > 65535) th16 = 65535;
            unsigned thp = (unsigned)th16 * 0x10001u;
            uint4 mv = t16[u];
            unsigned f0 = __vcmpgtu2(thp, mv.x);   // 0xffff where th16 > m16 (fail)
            unsigned f1 = __vcmpgtu2(thp, mv.y);
            unsigned f2 = __vcmpgtu2(thp, mv.z);
            unsigned f3 = __vcmpgtu2(thp, mv.w);
            if ((f0 & f1 & f2 & f3) != 0xFFFFFFFFu) {
                unsigned words[4] = {mv.x, mv.y, mv.z, mv.w};
                const int nb = u * 8;
                #pragma unroll
                for (int w_ = 0; w_ < 4; w_++) {
                    int mA = (int)(words[w_] & 0xffffu);
                    int mB = (int)(words[w_] >> 16);
                    if (mA >= th16) amx_surv(mrow, mmax, base, nb + 2*w_,     &s_uthm, lbest, libest);
                    if (mB >= th16) amx_surv(mrow, mmax, base, nb + 2*w_ + 1, &s_uthm, lbest, libest);
                }
            }
        }
    }

    szred[tid] = lbest; sired[tid] = libest;
    __syncthreads();
    for (int s = 128; s > 0; s >>= 1) {
        if (tid < s) {
            float oz = szred[tid + s]; int oi = sired[tid + s];
            if (oz > szred[tid] || (oz == szred[tid] && oi < sired[tid])) {
                szred[tid] = oz; sired[tid] = oi;
            }
        }
        __syncthreads();
    }
    if (tid == 0) g_sel[row] = sired[0];
}

// ---------------- K5: on-demand V rows + scores + softmax + context ----------------
__global__ __launch_bounds__(128) void k_context(const float* __restrict__ ge,
                                                 const float* __restrict__ Wv,
                                                 const float* __restrict__ bv,
                                                 float* __restrict__ out) {
    const int b = blockIdx.x, d = threadIdx.x;
    const int lane = d & 31, w = d >> 5;
    __shared__ int ssel[KSEL_];
    __shared__ __align__(16) float ges[KSEL_][256];
    __shared__ float part[4][KSEL_];
    __shared__ float ssc[KSEL_];
    if (d < KSEL_) ssel[d] = g_sel[b * KSEL_ + d];
    __syncthreads();
    for (int i = d; i < KSEL_ * 64; i += 128) {
        int k = i >> 6, c = i & 63;
        *(float4*)&ges[k][c * 4] = *(const float4*)(ge + ssel[k] * F2_ + c * 4);
    }
    __syncthreads();

    float v[KSEL_];
    const float bvd = bv[d];
    #pragma unroll
    for (int k = 0; k < KSEL_; k++) v[k] = bvd;
    for (int f = 0; f < F2_; f++) {
        const float wv = Wv[f * D_ + d];
        #pragma unroll
        for (int k = 0; k < KSEL_; k++) v[k] = fmaf(ges[k][f], wv, v[k]);
    }

    const float q = g_Q[b * D_ + d];
    #pragma unroll
    for (int k = 0; k < KSEL_; k++) {
        float p = q * v[k];
        p += __shfl_down_sync(0xffffffffu, p, 16);
        p += __shfl_down_sync(0xffffffffu, p, 8);
        p += __shfl_down_sync(0xffffffffu, p, 4);
        p += __shfl_down_sync(0xffffffffu, p, 2);
        p += __shfl_down_sync(0xffffffffu, p, 1);
        if (lane == 0) part[w][k] = p;
    }
    __syncthreads();
    if (d < KSEL_)
        ssc[d] = (part[0][d] + part[1][d] + part[2][d] + part[3][d]) / sqrtf(128.0f);
    __syncthreads();
    float mx = -1e30f;
    #pragma unroll
    for (int k = 0; k < KSEL_; k++) mx = fmaxf(mx, ssc[k]);
    float e[KSEL_], sum = 0.f;
    #pragma unroll
    for (int k = 0; k < KSEL_; k++) { e[k] = expf(ssc[k] - mx); sum += e[k]; }
    const float inv = 1.0f / sum;
    float ctx = 0.f;
    #pragma unroll
    for (int k = 0; k < KSEL_; k++) ctx = fmaf(e[k] * inv, v[k], ctx);
    out[b * D_ + d] = ctx;
}

// ---------------- stream/event context (created once, outside capture) ----------------
struct HxStreams {
    cudaStream_t s2;
    cudaEvent_t evFork, evJoin;
    HxStreams() {
        cudaStreamCreateWithFlags(&s2, cudaStreamNonBlocking);
        cudaEventCreateWithFlags(&evFork, cudaEventDisableTiming);
        cudaEventCreateWithFlags(&evJoin, cudaEventDisableTiming);
    }
};

// ---------------- launch ----------------
extern "C" void kernel_launch(void* const* d_in, const int* in_sizes, int n_in,
                              void* d_out, int out_size) {
    const float* pe = (const float*)d_in[0];
    const float* ge = (const float*)d_in[1];
    const float* Wq = (const float*)d_in[2];
    const float* bq = (const float*)d_in[3];
    const float* Wk = (const float*)d_in[4];
    const float* bk = (const float*)d_in[5];
    const float* Wv = (const float*)d_in[6];
    const float* bv = (const float*)d_in[7];
    const float* W1 = (const float*)d_in[8];
    const float* b1 = (const float*)d_in[9];
    const float* w2 = (const float*)d_in[10];
    const float* b2 = (const float*)d_in[11];

    static HxStreams hx;   // constructed on first (uncaptured) call

    // fork: hash table generation runs concurrently on s2
    cudaEventRecord(hx.evFork, 0);
    cudaStreamWaitEvent(hx.s2, hx.evFork, 0);
    k_hash<<<ROWS_ * 8, 256, 0, hx.s2>>>(1u);
    cudaEventRecord(hx.evJoin, hx.s2);

    // main stream: fp pipeline (fma-bound -> complements hash's alu load)
    k_prep<<<321, 128>>>(pe, Wq, bq, Wk, bk, W1, b1);
    k_gene<<<N_ / 32, 128>>>(ge);
    k_logits<<<dim3(40, 16), 128>>>(w2, b2);

    // join: argmax needs both the table (s2) and g_m/g_mmax (main)
    cudaStreamWaitEvent(0, hx.evJoin, 0);
    k_amx_lite<<<ROWS_, 256>>>();
    k_context<<<B_, 128>>>(ge, Wv, bv, (float*)d_out);
}

// round 16
// speedup vs baseline: 1.2746x; 1.2746x over previous
#include <cuda_runtime.h>
#include <cstdint>
#include <math.h>

#define B_    64
#define N_    20000
#define F1_   512
#define F2_   256
#define D_    128
#define KSEL_ 20
#define ROWS_ (B_ * KSEL_)

typedef unsigned long long u64t;

// ---------------- static device scratch (no allocations allowed) ----------------
__device__ float    g_kpbT[D_ * N_];     // TRANSPOSED: [d][n]
__device__ float    g_Q[B_ * D_];        // Q = pe@Wq + bq
__device__ float    g_qp2f[D_ * B_];     // q_part, packed layout [d][b]
__device__ float    g_m[B_ * N_];        // logits = sim / TEMP
__device__ unsigned g_mmax_bits[B_];     // per-b max of logits, encoded
__device__ int      g_sel[ROWS_];        // argmax indices
__device__ __align__(16) float g_Wf4[64 * D_ * 4];  // fused weight, packed [f4][d][4]
__device__ float    g_bias[D_];          // bk@W1[D:] + b1

// ---------------- f32x2 packed helpers ----------------
__device__ __forceinline__ u64t pack2(float lo, float hi) {
    u64t r; asm("mov.b64 %0,{%1,%2};" : "=l"(r) : "f"(lo), "f"(hi)); return r;
}
__device__ __forceinline__ float2 unpack2(u64t v) {
    float2 r; asm("mov.b64 {%0,%1},%2;" : "=f"(r.x), "=f"(r.y) : "l"(v)); return r;
}
__device__ __forceinline__ u64t add2(u64t a, u64t b) {
    u64t r; asm("add.rn.f32x2 %0,%1,%2;" : "=l"(r) : "l"(a), "l"(b)); return r;
}
__device__ __forceinline__ u64t fma2(u64t a, u64t b, u64t c) {
    u64t r; asm("fma.rn.f32x2 %0,%1,%2,%3;" : "=l"(r) : "l"(a), "l"(b), "l"(c)); return r;
}
__device__ __forceinline__ u64t abs2(u64t a) { return a & 0x7FFFFFFF7FFFFFFFULL; }

__device__ __forceinline__ unsigned enc_f(float z) {
    unsigned u = __float_as_uint(z);
    return (u & 0x80000000u) ? ~u : (u | 0x80000000u);
}
__device__ __forceinline__ float dec_f(unsigned e) {
    unsigned u = (e & 0x80000000u) ? (e & 0x7fffffffu) : ~e;
    return __uint_as_float(u);
}

// ---------------- K0: reset per-b max (tiny; also pads launch order) ----------------
__global__ __launch_bounds__(64) void k_init() {
    g_mmax_bits[threadIdx.x] = 0u;
}

// ---------------- K1a: Q + q_part ----------------
__global__ __launch_bounds__(128) void k_prep_q(const float* __restrict__ pe,
                                                const float* __restrict__ Wq,
                                                const float* __restrict__ bq,
                                                const float* __restrict__ W1) {
    __shared__ float pes[F1_];
    __shared__ float Qs[D_];
    const int b = blockIdx.x, d = threadIdx.x;
    for (int i = d; i < F1_; i += 128) pes[i] = pe[b * F1_ + i];
    __syncthreads();
    float acc = bq[d];
    #pragma unroll 4
    for (int f = 0; f < F1_; f++) acc = fmaf(pes[f], Wq[f * D_ + d], acc);
    g_Q[b * D_ + d] = acc;
    Qs[d] = acc;
    __syncthreads();
    float a2 = 0.f;
    #pragma unroll 4
    for (int j = 0; j < D_; j++) a2 = fmaf(Qs[j], W1[j * D_ + d], a2);
    g_qp2f[d * B_ + b] = a2;
}

// ---------------- K1b: fused weight Wf = Wk @ W1[D:] (packed f4 layout), bias ----------------
__global__ __launch_bounds__(128) void k_prep_w(const float* __restrict__ Wk,
                                                const float* __restrict__ bk,
                                                const float* __restrict__ W1,
                                                const float* __restrict__ b1) {
    __shared__ float rowv[D_];
    const int d = threadIdx.x;
    const float* W1p = W1 + D_ * D_;
    if (blockIdx.x < 256) {
        const int f = blockIdx.x;
        rowv[d] = Wk[f * D_ + d];
        __syncthreads();
        float acc = 0.f;
        #pragma unroll 4
        for (int j = 0; j < D_; j++) acc = fmaf(rowv[j], W1p[j * D_ + d], acc);
        g_Wf4[(((f >> 2) * D_) + d) * 4 + (f & 3)] = acc;
    } else {
        rowv[d] = bk[d];
        __syncthreads();
        float acc = b1[d];
        #pragma unroll 4
        for (int j = 0; j < D_; j++) acc = fmaf(rowv[j], W1p[j * D_ + d], acc);
        g_bias[d] = acc;
    }
}

// ---------------- K2: kpbT = (ge @ Wf + bias)^T -- row-pair f32x2, pack-free inner loop ----
// acc[p] lanes = rows (2p, 2p+1) of column d. Weight duplicated once per f4 (4 packs
// amortized over 16 row-pairs); gene data staged PRE-PACKED -> broadcast LDS.128.
// Per-element fma order identical to scalar version (bias, f ascending) -> bit-identical.
__global__ __launch_bounds__(128) void k_gene(const float* __restrict__ ge) {
    __shared__ __align__(16) u64t sg[16][256];    // row-pair packed gene tile, 32 KB
    const int d = threadIdx.x;
    const int n0 = blockIdx.x * 32;

    // stage: thread i handles (pair p, f4 c): loads 2 rows' float4, writes 4 packed u64t
    for (int i = d; i < 16 * 64; i += 128) {
        int p = i >> 6, c = i & 63;
        const float4 a = *(const float4*)(ge + (n0 + 2 * p) * F2_ + 4 * c);
        const float4 b = *(const float4*)(ge + (n0 + 2 * p + 1) * F2_ + 4 * c);
        sg[p][4 * c + 0] = pack2(a.x, b.x);
        sg[p][4 * c + 1] = pack2(a.y, b.y);
        sg[p][4 * c + 2] = pack2(a.z, b.z);
        sg[p][4 * c + 3] = pack2(a.w, b.w);
    }
    __syncthreads();

    u64t acc[16];
    const float bd = g_bias[d];
    const u64t bd2 = pack2(bd, bd);
    #pragma unroll
    for (int p = 0; p < 16; p++) acc[p] = bd2;

    const float4* Wf4 = (const float4*)g_Wf4;
    for (int f4 = 0; f4 < 64; f4++) {
        const float4 w = Wf4[f4 * D_ + d];        // coalesced LDG.128
        const u64t w0 = pack2(w.x, w.x), w1 = pack2(w.y, w.y);
        const u64t w2_ = pack2(w.z, w.z), w3 = pack2(w.w, w.w);
        #pragma unroll
        for (int p = 0; p < 16; p++) {
            ulonglong2 xa = *(const ulonglong2*)&sg[p][4 * f4];      // broadcast LDS.128
            ulonglong2 xb = *(const ulonglong2*)&sg[p][4 * f4 + 2];  // broadcast LDS.128
            acc[p] = fma2(xa.x, w0, acc[p]);
            acc[p] = fma2(xa.y, w1, acc[p]);
            acc[p] = fma2(xb.x, w2_, acc[p]);
            acc[p] = fma2(xb.y, w3, acc[p]);
        }
    }

    // epilogue: build float4 runs of consecutive n directly from register pairs
    float* dst = g_kpbT + d * N_ + n0;
    #pragma unroll
    for (int j = 0; j < 8; j++) {
        float2 aa = unpack2(acc[2 * j]);
        float2 bb = unpack2(acc[2 * j + 1]);
        float4 v; v.x = aa.x; v.y = aa.y; v.z = bb.x; v.w = bb.y;
        *(float4*)(dst + 4 * j) = v;
    }
}

// ---------------- K3: logits m[b,n] -- 4 b x 4 n per thread, pipelined d-loop ----------------
// lrelu(x) = 0.55x + 0.45|x| -> w*lrelu(x) = (0.55w)x + (0.45w)|x|
__global__ __launch_bounds__(128) void k_logits(const float* __restrict__ w2,
                                                const float* __restrict__ b2p) {
    __shared__ u64t s_q2[D_][4];
    __shared__ u64t s_wa[D_], s_wb[D_];
    const int tid = threadIdx.x;
    const int lane = tid & 31;
    const int b0 = blockIdx.y * 4;

    for (int i = tid; i < 512; i += 128) {
        int d = i >> 2, j = i & 3;
        float q = g_qp2f[d * B_ + b0 + j];
        s_q2[d][j] = pack2(q, q);
    }
    {
        float w = w2[tid];
        s_wa[tid] = pack2(0.55f * w, 0.55f * w);
        s_wb[tid] = pack2(0.45f * w, 0.45f * w);
    }
    __syncthreads();

    const int n = (blockIdx.x * 128 + tid) * 4;
    const int nc = n <= N_ - 4 ? n : N_ - 4;
    const float* kT = g_kpbT + nc;

    u64t accA[4][2], accB[4][2];
    #pragma unroll
    for (int b = 0; b < 4; b++) { accA[b][0]=accA[b][1]=0ull; accB[b][0]=accB[b][1]=0ull; }

    float4 kc[4];
    #pragma unroll
    for (int i = 0; i < 4; i++) kc[i] = *(const float4*)(kT + i * N_);

    #pragma unroll 2
    for (int d0 = 0; d0 < D_ - 4; d0 += 4) {
        float4 cur[4];
        #pragma unroll
        for (int i = 0; i < 4; i++) cur[i] = kc[i];
        #pragma unroll
        for (int i = 0; i < 4; i++) kc[i] = *(const float4*)(kT + (d0 + 4 + i) * N_);
        #pragma unroll
        for (int i = 0; i < 4; i++) {
            const int d = d0 + i;
            u64t kn01 = pack2(cur[i].x, cur[i].y);
            u64t kn23 = pack2(cur[i].z, cur[i].w);
            u64t wa = s_wa[d], wb = s_wb[d];
            #pragma unroll
            for (int b = 0; b < 4; b++) {
                u64t q = s_q2[d][b];
                u64t x0 = add2(q, kn01);
                u64t x1 = add2(q, kn23);
                accA[b][0] = fma2(x0, wa, accA[b][0]);
                accB[b][0] = fma2(abs2(x0), wb, accB[b][0]);
                accA[b][1] = fma2(x1, wa, accA[b][1]);
                accB[b][1] = fma2(abs2(x1), wb, accB[b][1]);
            }
        }
    }
    #pragma unroll
    for (int i = 0; i < 4; i++) {
        const int d = D_ - 4 + i;
        u64t kn01 = pack2(kc[i].x, kc[i].y);
        u64t kn23 = pack2(kc[i].z, kc[i].w);
        u64t wa = s_wa[d], wb = s_wb[d];
        #pragma unroll
        for (int b = 0; b < 4; b++) {
            u64t q = s_q2[d][b];
            u64t x0 = add2(q, kn01);
            u64t x1 = add2(q, kn23);
            accA[b][0] = fma2(x0, wa, accA[b][0]);
            accB[b][0] = fma2(abs2(x0), wb, accB[b][0]);
            accA[b][1] = fma2(x1, wa, accA[b][1]);
            accB[b][1] = fma2(abs2(x1), wb, accB[b][1]);
        }
    }

    const float b2 = *b2p;
    float vals[4][4];
    #pragma unroll
    for (int b = 0; b < 4; b++) {
        float2 a01 = unpack2(add2(accA[b][0], accB[b][0]));
        float2 a23 = unpack2(add2(accA[b][1], accB[b][1]));
        vals[b][0] = (a01.x + b2) * 2.0f;   // /TEMP, TEMP=0.5
        vals[b][1] = (a01.y + b2) * 2.0f;
        vals[b][2] = (a23.x + b2) * 2.0f;
        vals[b][3] = (a23.y + b2) * 2.0f;
    }
    if (n <= N_ - 4) {
        #pragma unroll
        for (int b = 0; b < 4; b++) {
            float4 v; v.x = vals[b][0]; v.y = vals[b][1]; v.z = vals[b][2]; v.w = vals[b][3];
            *(float4*)(g_m + (b0 + b) * N_ + n) = v;
        }
    }
    #pragma unroll
    for (int b = 0; b < 4; b++) {
        float m = fmaxf(fmaxf(vals[b][0], vals[b][1]), fmaxf(vals[b][2], vals[b][3]));
        m = fmaxf(m, __shfl_xor_sync(0xffffffffu, m, 16));
        m = fmaxf(m, __shfl_xor_sync(0xffffffffu, m, 8));
        m = fmaxf(m, __shfl_xor_sync(0xffffffffu, m, 4));
        m = fmaxf(m, __shfl_xor_sync(0xffffffffu, m, 2));
        m = fmaxf(m, __shfl_xor_sync(0xffffffffu, m, 1));
        if (lane == 0) atomicMax(&g_mmax_bits[b0 + b], enc_f(m));
    }
}

// ---------------- K4: gumbel argmax (R11-proven version, 94.8us) ----------------
__device__ __forceinline__ unsigned madu(unsigned a, unsigned one, unsigned c) {
    unsigned r; asm("mad.lo.s32 %0,%1,%2,%3;" : "=r"(r) : "r"(a), "r"(one), "r"(c)); return r;
}
#define TFRM(r) { x0 = madu(x1, one, x0); x1 = __funnelshift_l(x1, x1, (r)); x1 ^= x0; }

__device__ __forceinline__ unsigned threefry_bits(unsigned idx, unsigned one) {
    const unsigned ks1 = 42u, ks2 = 0x1BD11BF0u;   // ks0 = 0
    unsigned x1r = idx + ks1;
    unsigned x0 = x1r;
    unsigned x1 = __funnelshift_l(x1r, x1r, 13) ^ x0;
    TFRM(15) TFRM(26) TFRM(6);
    x0 = madu(ks1, one, x0);  x1 = madu(ks2 + 1u, one, x1);
    TFRM(17) TFRM(29) TFRM(16) TFRM(24);
    x0 = madu(ks2, one, x0);  x1 = madu(2u, one, x1);
    TFRM(13) TFRM(15) TFRM(26) TFRM(6);
    x1 = madu(ks1 + 3u, one, x1);   // x0 += 0
    TFRM(17) TFRM(29) TFRM(16) TFRM(24);
    x0 = madu(ks1, one, x0);  x1 = madu(ks2 + 4u, one, x1);
    TFRM(13) TFRM(15) TFRM(26) TFRM(6);
    x0 = madu(ks2, one, x0);  x1 = madu(5u, one, x1);
    return x0 ^ x1;
}

__device__ __forceinline__ void argmax_step(const float* __restrict__ mrow,
                                            float mmax, unsigned one,
                                            int n, unsigned idx,
                                            volatile int* s_uthm, int* s_uthm_nv,
                                            float& lbest, int& libest) {
    const int uthm = *s_uthm;
    unsigned bits = threefry_bits(idx, one);
    int mant = (int)(bits >> 9);
    if (mant > uthm) {
        float u = fmaxf(__uint_as_float((unsigned)mant | 0x3f800000u) - 1.0f,
                        1.17549435e-38f);
        float g = -logf(-logf(u));          // bit-matches XLA path
        float z = mrow[n] + g;
        if (z > lbest || (z == lbest && n < libest)) {
            lbest = z; libest = n;
            float nuth = expf(-expf(-(z - mmax))) - 2e-6f;
            if (nuth > 0.f) atomicMax(s_uthm_nv, (int)(nuth * 8388608.0f));
        }
    }
}

__global__ __launch_bounds__(256) void k_argmax() {
    const int row = blockIdx.x;            // b*KSEL + k
    const int b = row / KSEL_;
    const float* mrow = g_m + b * N_;
    const unsigned eb = g_mmax_bits[b];
    const float mmax = dec_f(eb);
    const unsigned one = (eb >> 31) | 1u;  // == 1 at runtime, opaque to ptxas
    __shared__ int s_uthm;
    __shared__ float szred[256];
    __shared__ int   sired[256];
    const int tid = threadIdx.x;
    if (tid == 0) s_uthm = -1;
    __syncthreads();

    const unsigned base = (unsigned)row * (unsigned)N_;
    float lbest = -1e30f;
    int   libest = 0x7fffffff;

    unsigned idx = base + (unsigned)tid;
    for (int j = 0; j < 78; j++, idx += 256u) {
        argmax_step(mrow, mmax, one, j * 256 + tid, idx,
                    (volatile int*)&s_uthm, &s_uthm, lbest, libest);
    }
    if (tid < N_ - 78 * 256) {
        argmax_step(mrow, mmax, one, 78 * 256 + tid, idx,
                    (volatile int*)&s_uthm, &s_uthm, lbest, libest);
    }
    szred[tid] = lbest; sired[tid] = libest;
    __syncthreads();
    for (int s = 128; s > 0; s >>= 1) {
        if (tid < s) {
            float oz = szred[tid + s]; int oi = sired[tid + s];
            if (oz > szred[tid] || (oz == szred[tid] && oi < sired[tid])) {
                szred[tid] = oz; sired[tid] = oi;
            }
        }
        __syncthreads();
    }
    if (tid == 0) g_sel[row] = sired[0];
}

// ---------------- K5: on-demand V rows + scores + softmax + context ----------------
__global__ __launch_bounds__(128) void k_context(const float* __restrict__ ge,
                                                 const float* __restrict__ Wv,
                                                 const float* __restrict__ bv,
                                                 float* __restrict__ out) {
    const int b = blockIdx.x, d = threadIdx.x;
    const int lane = d & 31, w = d >> 5;
    __shared__ int ssel[KSEL_];
    __shared__ __align__(16) float ges[KSEL_][256];
    __shared__ float part[4][KSEL_];
    __shared__ float ssc[KSEL_];
    if (d < KSEL_) ssel[d] = g_sel[b * KSEL_ + d];
    __syncthreads();
    for (int i = d; i < KSEL_ * 64; i += 128) {
        int k = i >> 6, c = i & 63;
        *(float4*)&ges[k][c * 4] = *(const float4*)(ge + ssel[k] * F2_ + c * 4);
    }
    __syncthreads();

    float v[KSEL_];
    const float bvd = bv[d];
    #pragma unroll
    for (int k = 0; k < KSEL_; k++) v[k] = bvd;
    for (int f = 0; f < F2_; f++) {
        const float wv = Wv[f * D_ + d];
        #pragma unroll
        for (int k = 0; k < KSEL_; k++) v[k] = fmaf(ges[k][f], wv, v[k]);
    }

    const float q = g_Q[b * D_ + d];
    #pragma unroll
    for (int k = 0; k < KSEL_; k++) {
        float p = q * v[k];
        p += __shfl_down_sync(0xffffffffu, p, 16);
        p += __shfl_down_sync(0xffffffffu, p, 8);
        p += __shfl_down_sync(0xffffffffu, p, 4);
        p += __shfl_down_sync(0xffffffffu, p, 2);
        p += __shfl_down_sync(0xffffffffu, p, 1);
        if (lane == 0) part[w][k] = p;
    }
    __syncthreads();
    if (d < KSEL_)
        ssc[d] = (part[0][d] + part[1][d] + part[2][d] + part[3][d]) / sqrtf(128.0f);
    __syncthreads();
    float mx = -1e30f;
    #pragma unroll
    for (int k = 0; k < KSEL_; k++) mx = fmaxf(mx, ssc[k]);
    float e[KSEL_], sum = 0.f;
    #pragma unroll
    for (int k = 0; k < KSEL_; k++) { e[k] = expf(ssc[k] - mx); sum += e[k]; }
    const float inv = 1.0f / sum;
    float ctx = 0.f;
    #pragma unroll
    for (int k = 0; k < KSEL_; k++) ctx = fmaf(e[k] * inv, v[k], ctx);
    out[b * D_ + d] = ctx;
}

// ---------------- launch ----------------
extern "C" void kernel_launch(void* const* d_in, const int* in_sizes, int n_in,
                              void* d_out, int out_size) {
    const float* pe = (const float*)d_in[0];
    const float* ge = (const float*)d_in[1];
    const float* Wq = (const float*)d_in[2];
    const float* bq = (const float*)d_in[3];
    const float* Wk = (const float*)d_in[4];
    const float* bk = (const float*)d_in[5];
    const float* Wv = (const float*)d_in[6];
    const float* bv = (const float*)d_in[7];
    const float* W1 = (const float*)d_in[8];
    const float* b1 = (const float*)d_in[9];
    const float* w2 = (const float*)d_in[10];
    const float* b2 = (const float*)d_in[11];

    k_init<<<1, 64>>>();                               // 1st
    k_prep_q<<<B_, 128>>>(pe, Wq, bq, W1);             // 2nd
    k_prep_w<<<257, 128>>>(Wk, bk, W1, b1);            // 3rd
    k_gene<<<N_ / 32, 128>>>(ge);                      // 4th -> profiled this round
    k_logits<<<dim3(40, 16), 128>>>(w2, b2);
    k_argmax<<<ROWS_, 256>>>();
    k_context<<<B_, 128>>>(ge, Wv, bv, (float*)d_out);
}